// round 1
// baseline (speedup 1.0000x reference)
#include <cuda_runtime.h>
#include <math.h>

#define BCAPS 32
#define CCAPS 32
#define HH    16
#define WIN   14
#define WOUT  6
#define WW    36            // WOUT*WOUT
#define BKK   288           // BCAPS*3*3
#define CWW   1152          // CCAPS*WW
#define NB    16            // batch
#define EPSV  1e-10f
#define RSQRT2PI 0.3989422804014327f

// ---------------- scratch (device globals; no runtime allocation) -------------
__device__ float g_PTm[NB*196*BCAPS*HH];   // pose [b][x*14+y][B][hh]   (M layout)
__device__ float g_PTe[NB*BCAPS*196*HH];   // pose [b][B][x*14+y][hh]   (E layout)
__device__ float g_WTm[CCAPS*BKK*HH];      // W    [c][bkk][hh]         (M layout)
__device__ float g_AW [NB*WW*BKK];         // act window [b][ww][bkk]
__device__ float g_RT [NB*CWW*BKK];        // R transposed [b][cww][bkk]
__device__ float g_AP [NB*BKK*WW*CCAPS];   // a*p   [b][bkk][ww][c]
__device__ float g_rowsum[NB*BKK];
__device__ float g_mu  [NB*WW*CCAPS*HH];   // [b][ww][c][hh]
__device__ float g_isig[NB*WW*CCAPS*HH];
__device__ float g_a   [NB*WW*CCAPS];

// ---------------- prep kernels -----------------------------------------------

// poses (b, hh*32+B, 14,14) -> PTm / PTe
__global__ __launch_bounds__(256) void prep_pose_kernel(const float* __restrict__ poses) {
    int B = blockIdx.x, b = blockIdx.y, t = threadIdx.x;
    __shared__ float tile[16*197];
    for (int idx = t; idx < 16*196; idx += 256) {
        int h = idx / 196, xy = idx % 196;
        tile[h*197 + xy] = poses[(b*512 + h*32 + B)*196 + xy];
    }
    __syncthreads();
    for (int idx = t; idx < 196*16; idx += 256) {
        int xy = idx >> 4, h = idx & 15;
        float v = tile[h*197 + xy];
        g_PTe[((b*32 + B)*196 + xy)*16 + h] = v;
        g_PTm[((b*196 + xy)*32 + B)*16 + h] = v;
    }
}

// W (bkk, c, 16) -> WTm (c, bkk, 16)
__global__ __launch_bounds__(256) void prep_W_kernel(const float* __restrict__ W) {
    int o = blockIdx.x*256 + threadIdx.x;   // < 147456
    int c = o / 4608;
    int r = o - c*4608;
    int bkk = r >> 4, h = r & 15;
    g_WTm[o] = W[(bkk*32 + c)*16 + h];
}

// activations (b, B, 14,14) -> AW [b][ww][bkk]
__global__ __launch_bounds__(256) void prep_AW_kernel(const float* __restrict__ act) {
    int idx = blockIdx.x*256 + threadIdx.x;
    if (idx >= NB*WW*BKK) return;
    int b = idx / (WW*BKK);
    int r = idx % (WW*BKK);
    int ww = r / BKK, bkk = r % BKK;
    int B = bkk / 9, kq = bkk % 9;
    int kx = kq / 3, ky = kq % 3;
    int wx = ww / 6, wy = ww % 6;
    g_AW[idx] = act[((b*32 + B)*14 + wx*2 + kx)*14 + wy*2 + ky];
}

// ---------------- M step ------------------------------------------------------
// One block per (b, c, wx, wy). Recomputes the 288x16 vote column from SMEM
// pose window + W slice; exact two-pass mu/sigma; fused cost -> a.
__global__ __launch_bounds__(256) void m_step_kernel(
    const float* __restrict__ beta_v, const float* __restrict__ beta_a,
    const float* __restrict__ lambda_, int first_iter, float* __restrict__ out) {
    int ww = blockIdx.x, c = blockIdx.y, b = blockIdx.z, t = threadIdx.x;
    int wx = ww / 6, wy = ww % 6;

    __shared__ float Psm[4608];    // [bkk][k*4+j]
    __shared__ float Wsm[4608];    // [bkk][i*4+k]
    __shared__ float rw [288];
    __shared__ float red[256];
    __shared__ float mu_s[16], costp[16];
    __shared__ float sumR_s;

    // pose window: 9 contiguous 512-float segments
    for (int idx = t; idx < 4608; idx += 256) {
        int kq = idx / 512, s = idx & 511;
        int B = s >> 4, h = s & 15;
        int x = wx*2 + kq/3, y = wy*2 + kq%3;
        Psm[B*144 + kq*16 + h] = g_PTm[((b*196 + x*14 + y)*32 + B)*16 + h];
    }
    const float* wsrc = &g_WTm[c*4608];
    for (int idx = t; idx < 4608; idx += 256) Wsm[idx] = wsrc[idx];

    // rw = R * act_window  (+ partial sums)
    float local_s = 0.f;
    const float* rrow = &g_RT[((size_t)b*CWW + c*36 + ww)*BKK];
    const float* arow = &g_AW[(b*WW + ww)*BKK];
    for (int idx = t; idx < 288; idx += 256) {
        float r = first_iter ? (1.0f/(float)CWW) : rrow[idx];
        float v = r * arow[idx];
        rw[idx] = v;
        local_s += v;
    }
    red[t] = local_s;
    __syncthreads();
    for (int s = 128; s > 0; s >>= 1) {
        if (t < s) red[t] += red[t + s];
        __syncthreads();
    }
    if (t == 0) sumR_s = red[0];
    __syncthreads();
    float sumR = sumR_s;

    int h = t & 15;
    int bkk_base = t >> 4;
    int irow4 = (h >> 2) * 4;
    int j = h & 3;

    // pass 1: votes (kept in registers) + weighted sum
    float vreg[18];
    float mu_acc = 0.f;
#pragma unroll
    for (int i = 0; i < 18; i++) {
        int bkk = bkk_base + i*16;
        const float* Wp = &Wsm[bkk*16 + irow4];
        const float* Pp = &Psm[bkk*16 + j];
        float v = Wp[0]*Pp[0] + Wp[1]*Pp[4] + Wp[2]*Pp[8] + Wp[3]*Pp[12];
        vreg[i] = v;
        mu_acc += rw[bkk] * v;
    }
    red[t] = mu_acc;
    __syncthreads();
    if (t < 16) {
        float s = 0.f;
#pragma unroll
        for (int g = 0; g < 16; g++) s += red[t + g*16];
        mu_s[t] = s / sumR;
    }
    __syncthreads();
    float mu_h = mu_s[h];

    // pass 2: variance
    float sg_acc = 0.f;
#pragma unroll
    for (int i = 0; i < 18; i++) {
        int bkk = bkk_base + i*16;
        float d = vreg[i] - mu_h;
        sg_acc += rw[bkk] * d * d;
    }
    red[t] = sg_acc;
    __syncthreads();
    if (t < 16) {
        float s = 0.f;
#pragma unroll
        for (int g = 0; g < 16; g++) s += red[t + g*16];
        float ssq = s / sumR;
        float sg  = sqrtf(ssq);
        costp[t] = logf(sg + EPSV);
        int o = ((b*WW + ww)*CCAPS + c)*16 + t;
        g_mu[o]   = mu_s[t];
        g_isig[o] = 1.0f / sg;
        if (out) out[((b*CCAPS + c)*WW + ww)*16 + t] = mu_s[t];
    }
    __syncthreads();
    if (t == 0) {
        float bv = beta_v[c];
        float cs = 0.f;
#pragma unroll
        for (int hh2 = 0; hh2 < 16; hh2++) cs += bv + costp[hh2];
        cs *= sumR;
        float lam = lambda_[0];
        float a = 1.0f / (1.0f + __expf(-lam * (beta_a[c] - cs)));
        g_a[(b*WW + ww)*CCAPS + c] = a;
        if (out) out[NB*CCAPS*WW*16 + (b*CCAPS + c)*WW + ww] = a;
    }
}

// ---------------- E step ------------------------------------------------------
// One block per (b, B). 9 warps = 9 kernel offsets, lane = output capsule c.
// W matrix lives in registers; pose + mu/isig tiles in SMEM; ap = a * sum_h N(V).
__global__ __launch_bounds__(288) void e_step_kernel(const float* __restrict__ W) {
    int B = blockIdx.x, b = blockIdx.y;
    int t = threadIdx.x;
    int warp = t >> 5, lane = t & 31;   // warp = (kx,ky), lane = c
    int bkk = B*9 + warp;
    int kx = warp / 3, ky = warp % 3;

    __shared__ float psm [196*16];
    __shared__ float musm[6*32*17];
    __shared__ float issm[6*32*17];
    __shared__ float a_sm[6*32];

    for (int idx = t; idx < 3136; idx += 288)
        psm[idx] = g_PTe[(size_t)(b*32 + B)*3136 + idx];

    float Wreg[16];
    const float* wp = &W[(bkk*32 + lane)*16];
#pragma unroll
    for (int q = 0; q < 4; q++) {
        float4 f = *reinterpret_cast<const float4*>(wp + q*4);
        Wreg[q*4+0] = f.x; Wreg[q*4+1] = f.y;
        Wreg[q*4+2] = f.z; Wreg[q*4+3] = f.w;
    }

    float rs_local = 0.f;
    for (int tile = 0; tile < 6; tile++) {       // tile == wx
        __syncthreads();
        for (int idx = t; idx < 6*32*16; idx += 288) {
            int wl = idx >> 9;
            int c2 = (idx >> 4) & 31;
            int h2 = idx & 15;
            int go = ((b*WW + tile*6 + wl)*CCAPS + c2)*16 + h2;
            musm[(wl*32 + c2)*17 + h2] = g_mu[go];
            issm[(wl*32 + c2)*17 + h2] = g_isig[go];
        }
        for (int idx = t; idx < 192; idx += 288) {
            int wl = idx >> 5, c2 = idx & 31;
            a_sm[idx] = g_a[(b*WW + tile*6 + wl)*CCAPS + c2];
        }
        __syncthreads();

        for (int wl = 0; wl < 6; wl++) {         // wl == wy
            int ww = tile*6 + wl;
            const float* pp = &psm[((2*tile + kx)*14 + 2*wl + ky)*16];
            float P[16];
#pragma unroll
            for (int q = 0; q < 16; q++) P[q] = pp[q];
            float V[16];
#pragma unroll
            for (int i = 0; i < 4; i++)
#pragma unroll
                for (int jj = 0; jj < 4; jj++)
                    V[i*4+jj] = Wreg[i*4+0]*P[jj]   + Wreg[i*4+1]*P[4+jj]
                              + Wreg[i*4+2]*P[8+jj] + Wreg[i*4+3]*P[12+jj];
            int base = (wl*32 + lane)*17;
            float p = 0.f;
#pragma unroll
            for (int h = 0; h < 16; h++) {
                float m  = musm[base + h];
                float is = issm[base + h];
                float z  = (V[h] + EPSV - m) * is;
                p += is * RSQRT2PI * __expf(-0.5f * z * z);
            }
            float ap = a_sm[wl*32 + lane] * p;
            g_AP[((size_t)(b*BKK + bkk)*WW + ww)*CCAPS + lane] = ap;
            rs_local += ap;
        }
    }
#pragma unroll
    for (int o = 16; o > 0; o >>= 1)
        rs_local += __shfl_xor_sync(0xffffffffu, rs_local, o);
    if (lane == 0) g_rowsum[b*BKK + bkk] = rs_local;
}

// ---------------- normalize + transpose: R = ap/rowsum + EPS -----------------
// AP [b][bkk][ww][c]  ->  RT [b][c*36+ww][bkk]   (32x32 SMEM tile transpose)
__global__ __launch_bounds__(256) void norm_kernel() {
    int ww = blockIdx.x, bt = blockIdx.y, b = blockIdx.z;
    int t = threadIdx.x;
    int tx = t & 31, ty = t >> 5;               // ty 0..7
    __shared__ float tile[32*33];
    __shared__ float rs[32];
    if (t < 32) rs[t] = g_rowsum[b*BKK + bt*32 + t];
    __syncthreads();
#pragma unroll
    for (int r = 0; r < 4; r++) {
        int bl = ty + r*8;
        float v = g_AP[((size_t)(b*BKK + bt*32 + bl)*WW + ww)*CCAPS + tx];
        tile[bl*33 + tx] = v / rs[bl] + EPSV;
    }
    __syncthreads();
#pragma unroll
    for (int r = 0; r < 4; r++) {
        int cc = ty + r*8;
        g_RT[((size_t)b*CWW + cc*36 + ww)*BKK + bt*32 + tx] = tile[tx*33 + cc];
    }
}

// ---------------- launch ------------------------------------------------------
extern "C" void kernel_launch(void* const* d_in, const int* in_sizes, int n_in,
                              void* d_out, int out_size) {
    const float* poses  = (const float*)d_in[0];
    const float* act    = (const float*)d_in[1];
    const float* W      = (const float*)d_in[2];
    const float* beta_v = (const float*)d_in[3];
    const float* beta_a = (const float*)d_in[4];
    const float* lam    = (const float*)d_in[5];
    float* out = (float*)d_out;

    prep_pose_kernel<<<dim3(32,16), 256>>>(poses);
    prep_W_kernel<<<576, 256>>>(W);
    prep_AW_kernel<<<(NB*WW*BKK + 255)/256, 256>>>(act);

    for (int it = 0; it < 3; it++) {
        m_step_kernel<<<dim3(36,32,16), 256>>>(beta_v, beta_a, lam,
                                               it == 0 ? 1 : 0,
                                               it == 2 ? out : (float*)nullptr);
        if (it < 2) {
            e_step_kernel<<<dim3(32,16), 288>>>(W);
            norm_kernel<<<dim3(36,9,16), 256>>>();
        }
    }
}

// round 2
// speedup vs baseline: 1.5231x; 1.5231x over previous
#include <cuda_runtime.h>
#include <math.h>

#define BCAPS 32
#define CCAPS 32
#define HH    16
#define WIN   14
#define WOUT  6
#define WW    36            // WOUT*WOUT
#define BKK   288           // BCAPS*3*3
#define CWW   1152          // CCAPS*WW
#define NB    16            // batch
#define EPSV  1e-10f
#define RSQRT2PI 0.3989422804014327f

// NOTE: internal "bkk" ordering everywhere below is bkk' = kq*32 + B
// (kernel-offset-major), so that lane index == B gives coalesced access.

// ---------------- scratch (device globals; no runtime allocation) -------------
__device__ float g_PTm[NB*196*BCAPS*HH];   // pose [b][x*14+y][B][hh]
__device__ float g_PTe[NB*BCAPS*196*HH];   // pose [b][B][x*14+y][hh]
__device__ float g_WTm[CCAPS*BKK*HH];      // W    [c][bkk'][hh]
__device__ float g_AW [NB*WW*BKK];         // act window [b][ww][bkk']
__device__ float g_RT [NB*CWW*BKK];        // R transposed [b][cww][bkk']
__device__ float g_AP [NB*BKK*WW*CCAPS];   // a*p   [b][bkk'][ww][c]
__device__ float g_rowsum[NB*BKK];
__device__ float g_mu  [NB*WW*CCAPS*HH];   // [b][ww][c][hh]
__device__ float g_isig[NB*WW*CCAPS*HH];
__device__ float g_a   [NB*WW*CCAPS];

// ---------------- prep kernels -----------------------------------------------

// poses (b, hh*32+B, 14,14) -> PTm / PTe
__global__ __launch_bounds__(256) void prep_pose_kernel(const float* __restrict__ poses) {
    int B = blockIdx.x, b = blockIdx.y, t = threadIdx.x;
    __shared__ float tile[16*197];
    for (int idx = t; idx < 16*196; idx += 256) {
        int h = idx / 196, xy = idx % 196;
        tile[h*197 + xy] = poses[(b*512 + h*32 + B)*196 + xy];
    }
    __syncthreads();
    for (int idx = t; idx < 196*16; idx += 256) {
        int xy = idx >> 4, h = idx & 15;
        float v = tile[h*197 + xy];
        g_PTe[((b*32 + B)*196 + xy)*16 + h] = v;
        g_PTm[((b*196 + xy)*32 + B)*16 + h] = v;
    }
}

// W (bkk=B*9+kq, c, 16) -> WTm [c][bkk'=kq*32+B][16]
__global__ __launch_bounds__(256) void prep_W_kernel(const float* __restrict__ W) {
    int o = blockIdx.x*256 + threadIdx.x;   // < 147456
    int c = o / 4608;
    int r = o - c*4608;
    int bkp = r >> 4, h = r & 15;
    int kq = bkp >> 5, B = bkp & 31;
    g_WTm[o] = W[((B*9 + kq)*32 + c)*16 + h];
}

// activations (b, B, 14,14) -> AW [b][ww][bkk']
__global__ __launch_bounds__(256) void prep_AW_kernel(const float* __restrict__ act) {
    int idx = blockIdx.x*256 + threadIdx.x;
    if (idx >= NB*WW*BKK) return;
    int b = idx / (WW*BKK);
    int r = idx % (WW*BKK);
    int ww = r / BKK, bkp = r % BKK;
    int kq = bkp >> 5, B = bkp & 31;
    int kx = kq / 3, ky = kq % 3;
    int wx = ww / 6, wy = ww % 6;
    g_AW[idx] = act[((b*32 + B)*14 + wx*2 + kx)*14 + wy*2 + ky];
}

// ---------------- M step ------------------------------------------------------
// One block per (b, c, ww). 288 threads = one bkk' each (warp = kq, lane = B).
// Votes recomputed in registers from coalesced L2 reads; single-pass
// mu / sigma via sums of rw, rw*V, rw*V^2; one padded SMEM reduction.
__global__ __launch_bounds__(288, 3) void m_step_kernel(
    const float* __restrict__ beta_v, const float* __restrict__ beta_a,
    const float* __restrict__ lambda_, int first_iter, float* __restrict__ out) {
    const int ww = blockIdx.x, c = blockIdx.y, b = blockIdx.z;
    const int t = threadIdx.x;
    const int warp = t >> 5, lane = t & 31;      // kq, B
    const int wx = ww / 6, wy = ww % 6;
    const int x = wx*2 + warp/3, y = wy*2 + warp%3;

    __shared__ float red[288*36];    // per-thread partials, pad 36 (conflict-free)
    __shared__ float seg2[9*32];     // [seg][v] second-level partials (S1)
    __shared__ float seg3[9*32];     // [seg][v] second-level partials (S2)
    __shared__ float wS0[9];

    // rw = R * act_window
    float aw = g_AW[(b*WW + ww)*BKK + t];
    float rr = first_iter ? (1.0f/(float)CWW)
                          : g_RT[((size_t)b*CWW + c*36 + ww)*BKK + t];
    float rw = rr * aw;

    // W row (16 floats) and pose row (16 floats), fully coalesced float4 loads
    const float4* wp = reinterpret_cast<const float4*>(&g_WTm[(c*BKK + t)*16]);
    float4 w0 = wp[0], w1 = wp[1], w2 = wp[2], w3 = wp[3];
    const float4* pp = reinterpret_cast<const float4*>(
        &g_PTm[((b*196 + x*14 + y)*32 + lane)*16]);
    float4 p0 = pp[0], p1 = pp[1], p2 = pp[2], p3 = pp[3];

    // votes V[i][j] = sum_k W[i][k] * P[k][j]
    float V[16];
    {
        float Wr[16] = {w0.x,w0.y,w0.z,w0.w, w1.x,w1.y,w1.z,w1.w,
                        w2.x,w2.y,w2.z,w2.w, w3.x,w3.y,w3.z,w3.w};
        float Pr[16] = {p0.x,p0.y,p0.z,p0.w, p1.x,p1.y,p1.z,p1.w,
                        p2.x,p2.y,p2.z,p2.w, p3.x,p3.y,p3.z,p3.w};
#pragma unroll
        for (int i = 0; i < 4; i++)
#pragma unroll
            for (int j = 0; j < 4; j++)
                V[i*4+j] = Wr[i*4+0]*Pr[j]   + Wr[i*4+1]*Pr[4+j]
                         + Wr[i*4+2]*Pr[8+j] + Wr[i*4+3]*Pr[12+j];
    }

    // emit rw*V (v=0..15) and rw*V^2 (v=16..31) as 8 conflict-free STS.128
    float* myrow = &red[t*36];
#pragma unroll
    for (int q = 0; q < 4; q++) {
        float4 s1, s2;
        s1.x = rw*V[q*4+0]; s1.y = rw*V[q*4+1];
        s1.z = rw*V[q*4+2]; s1.w = rw*V[q*4+3];
        s2.x = s1.x*V[q*4+0]; s2.y = s1.y*V[q*4+1];
        s2.z = s1.z*V[q*4+2]; s2.w = s1.w*V[q*4+3];
        *reinterpret_cast<float4*>(myrow + q*4)      = s1;
        *reinterpret_cast<float4*>(myrow + 16 + q*4) = s2;
    }

    // S0 = sum rw  (warp shuffle, then 9 partials)
    float s0 = rw;
#pragma unroll
    for (int o = 16; o > 0; o >>= 1) s0 += __shfl_xor_sync(0xffffffffu, s0, o);
    if (lane == 0) wS0[warp] = s0;
    __syncthreads();

    // level-1 reduce: thread (seg=warp, v=lane) sums 32 bkk rows
    {
        float a1 = 0.f, a2 = 0.f;
        const float* base = &red[(warp*32)*36];
#pragma unroll
        for (int i = 0; i < 32; i++) {
            a1 += base[i*36 + lane];
            a2 += base[i*36 + 16 + lane];
        }
        // lane v sums S1-part for v (a1 uses +lane offsets 0..15 when lane<16,
        // 16..31 when lane>=16 -> we just keep both halves separately:
        seg2[warp*32 + lane] = a1;     // value index = lane (0..31): 0-15 S1, 16-31 S2... 
        seg3[warp*32 + lane] = a2;     // value index = lane+16 folded; see below
    }
    __syncthreads();

    // Final: threads 0..15 own h. S1[h] lives at value-index h, S2[h] at h+16.
    // a1 covered value v=lane; a2 covered value v=16+lane (mod 32 wrap for lane>=16:
    // lane>=16 -> a1 is S2[lane-16], a2 is S1[lane-16]... resolve explicitly:
    //   a1(lane) = sum over rows of red[row*36 + lane]        -> value index lane
    //   a2(lane) = sum over rows of red[row*36 + 16 + lane]   -> value index 16+lane
    // For lane >= 16, 16+lane >= 32 reads red[row*36 + 16+lane] which is PAST the
    // 32 valid values (indices 32..47 within the 36-pad row) -> garbage.
    // So: S1[h] = seg2[seg*32+h] summed; S2[h] = seg3[seg*32+h] summed (lane<16 half).
    float S0 = 0.f;
#pragma unroll
    for (int s = 0; s < 9; s++) S0 += wS0[s];

    float costp = 0.f;
    float mu_h = 0.f, isig_h = 0.f;
    if (t < 16) {
        float S1 = 0.f, S2 = 0.f;
#pragma unroll
        for (int s = 0; s < 9; s++) { S1 += seg2[s*32 + t]; S2 += seg3[s*32 + t]; }
        float mu = S1 / S0;
        float varr = fmaxf(S2 / S0 - mu*mu, 1e-30f);
        float sg = sqrtf(varr);
        mu_h = mu; isig_h = 1.0f / sg;
        costp = logf(sg + EPSV);
        int o = ((b*WW + ww)*CCAPS + c)*16 + t;
        g_mu[o]   = mu;
        g_isig[o] = isig_h;
        if (out) out[((b*CCAPS + c)*WW + ww)*16 + t] = mu;
    }
    // cost sum over h within lanes 0..15 of warp 0
    if (warp == 0) {
        float cs = costp;
#pragma unroll
        for (int o = 8; o > 0; o >>= 1) cs += __shfl_xor_sync(0xffffffffu, cs, o);
        if (lane == 0) {
            float bv = beta_v[c];
            float total = (cs + 16.0f*bv) * S0;
            float lam = lambda_[0];
            float a = 1.0f / (1.0f + __expf(-lam * (beta_a[c] - total)));
            g_a[(b*WW + ww)*CCAPS + c] = a;
            if (out) out[NB*CCAPS*WW*16 + (b*CCAPS + c)*WW + ww] = a;
        }
    }
}

// ---------------- E step ------------------------------------------------------
// One block per (b, B). 9 warps = 9 kernel offsets, lane = output capsule c.
__global__ __launch_bounds__(288) void e_step_kernel(const float* __restrict__ W) {
    int B = blockIdx.x, b = blockIdx.y;
    int t = threadIdx.x;
    int warp = t >> 5, lane = t & 31;   // warp = kq, lane = c
    int bkk_in  = B*9 + warp;           // input-W ordering
    int bkk_out = warp*32 + B;          // internal bkk' ordering
    int kx = warp / 3, ky = warp % 3;

    __shared__ float psm [196*16];
    __shared__ float musm[6*32*17];
    __shared__ float issm[6*32*17];
    __shared__ float a_sm[6*32];

    for (int idx = t; idx < 3136; idx += 288)
        psm[idx] = g_PTe[(size_t)(b*32 + B)*3136 + idx];

    float Wreg[16];
    const float* wp = &W[(bkk_in*32 + lane)*16];
#pragma unroll
    for (int q = 0; q < 4; q++) {
        float4 f = *reinterpret_cast<const float4*>(wp + q*4);
        Wreg[q*4+0] = f.x; Wreg[q*4+1] = f.y;
        Wreg[q*4+2] = f.z; Wreg[q*4+3] = f.w;
    }

    float rs_local = 0.f;
    for (int tile = 0; tile < 6; tile++) {       // tile == wx
        __syncthreads();
        for (int idx = t; idx < 6*32*16; idx += 288) {
            int wl = idx >> 9;
            int c2 = (idx >> 4) & 31;
            int h2 = idx & 15;
            int go = ((b*WW + tile*6 + wl)*CCAPS + c2)*16 + h2;
            musm[(wl*32 + c2)*17 + h2] = g_mu[go];
            issm[(wl*32 + c2)*17 + h2] = g_isig[go];
        }
        for (int idx = t; idx < 192; idx += 288) {
            int wl = idx >> 5, c2 = idx & 31;
            a_sm[idx] = g_a[(b*WW + tile*6 + wl)*CCAPS + c2];
        }
        __syncthreads();

        for (int wl = 0; wl < 6; wl++) {         // wl == wy
            int ww = tile*6 + wl;
            const float* pp = &psm[((2*tile + kx)*14 + 2*wl + ky)*16];
            float P[16];
#pragma unroll
            for (int q = 0; q < 16; q++) P[q] = pp[q];
            float V[16];
#pragma unroll
            for (int i = 0; i < 4; i++)
#pragma unroll
                for (int jj = 0; jj < 4; jj++)
                    V[i*4+jj] = Wreg[i*4+0]*P[jj]   + Wreg[i*4+1]*P[4+jj]
                              + Wreg[i*4+2]*P[8+jj] + Wreg[i*4+3]*P[12+jj];
            int base = (wl*32 + lane)*17;
            float p = 0.f;
#pragma unroll
            for (int h = 0; h < 16; h++) {
                float m  = musm[base + h];
                float is = issm[base + h];
                float z  = (V[h] + EPSV - m) * is;
                p += is * RSQRT2PI * __expf(-0.5f * z * z);
            }
            float ap = a_sm[wl*32 + lane] * p;
            g_AP[((size_t)(b*BKK + bkk_out)*WW + ww)*CCAPS + lane] = ap;
            rs_local += ap;
        }
    }
#pragma unroll
    for (int o = 16; o > 0; o >>= 1)
        rs_local += __shfl_xor_sync(0xffffffffu, rs_local, o);
    if (lane == 0) g_rowsum[b*BKK + bkk_out] = rs_local;
}

// ---------------- normalize + transpose: R = ap/rowsum + EPS -----------------
// AP [b][bkk'][ww][c]  ->  RT [b][c*36+ww][bkk']
__global__ __launch_bounds__(256) void norm_kernel() {
    int ww = blockIdx.x, bt = blockIdx.y, b = blockIdx.z;
    int t = threadIdx.x;
    int tx = t & 31, ty = t >> 5;               // ty 0..7
    __shared__ float tile[32*33];
    __shared__ float rs[32];
    if (t < 32) rs[t] = g_rowsum[b*BKK + bt*32 + t];
    __syncthreads();
#pragma unroll
    for (int r = 0; r < 4; r++) {
        int bl = ty + r*8;
        float v = g_AP[((size_t)(b*BKK + bt*32 + bl)*WW + ww)*CCAPS + tx];
        tile[bl*33 + tx] = v / rs[bl] + EPSV;
    }
    __syncthreads();
#pragma unroll
    for (int r = 0; r < 4; r++) {
        int cc = ty + r*8;
        g_RT[((size_t)b*CWW + cc*36 + ww)*BKK + bt*32 + tx] = tile[tx*33 + cc];
    }
}

// ---------------- launch ------------------------------------------------------
extern "C" void kernel_launch(void* const* d_in, const int* in_sizes, int n_in,
                              void* d_out, int out_size) {
    const float* poses  = (const float*)d_in[0];
    const float* act    = (const float*)d_in[1];
    const float* W      = (const float*)d_in[2];
    const float* beta_v = (const float*)d_in[3];
    const float* beta_a = (const float*)d_in[4];
    const float* lam    = (const float*)d_in[5];
    float* out = (float*)d_out;

    prep_pose_kernel<<<dim3(32,16), 256>>>(poses);
    prep_W_kernel<<<576, 256>>>(W);
    prep_AW_kernel<<<(NB*WW*BKK + 255)/256, 256>>>(act);

    for (int it = 0; it < 3; it++) {
        m_step_kernel<<<dim3(36,32,16), 288>>>(beta_v, beta_a, lam,
                                               it == 0 ? 1 : 0,
                                               it == 2 ? out : (float*)nullptr);
        if (it < 2) {
            e_step_kernel<<<dim3(32,16), 288>>>(W);
            norm_kernel<<<dim3(36,9,16), 256>>>();
        }
    }
}

// round 3
// speedup vs baseline: 1.8719x; 1.2290x over previous
#include <cuda_runtime.h>
#include <math.h>

#define BCAPS 32
#define CCAPS 32
#define HH    16
#define WIN   14
#define WOUT  6
#define WW    36            // WOUT*WOUT
#define BKK   288           // BCAPS*3*3
#define CWW   1152          // CCAPS*WW
#define NB    16            // batch
#define EPSV  1e-10f
#define RSQRT2PI 0.3989422804014327f

// internal "bkk" ordering: bkk' = kq*32 + B (kernel-offset-major)

// ---------------- scratch ----------------------------------------------------
__device__ float g_PTm[NB*196*BCAPS*HH];   // pose [b][x*14+y][B][hh]
__device__ float g_PTe[NB*BCAPS*196*HH];   // pose [b][B][x*14+y][hh]
__device__ float g_WTm[CCAPS*BKK*HH];      // W    [c][bkk'][hh]
__device__ float g_AW [NB*WW*BKK];         // act window [b][ww][bkk']
__device__ float g_RT [NB*CWW*BKK];        // R transposed [b][cww][bkk']
__device__ float g_AP [NB*BKK*WW*CCAPS];   // a*p   [b][bkk'][ww][c]
__device__ float g_rowsum[NB*BKK];
__device__ float g_mu  [NB*WW*CCAPS*HH];   // [b][ww][c][hh]
__device__ float g_isig[NB*WW*CCAPS*HH];
__device__ float g_a   [NB*WW*CCAPS];

// ---------------- prep kernels -----------------------------------------------
__global__ __launch_bounds__(256) void prep_pose_kernel(const float* __restrict__ poses) {
    int B = blockIdx.x, b = blockIdx.y, t = threadIdx.x;
    __shared__ float tile[16*197];
    for (int idx = t; idx < 16*196; idx += 256) {
        int h = idx / 196, xy = idx % 196;
        tile[h*197 + xy] = poses[(b*512 + h*32 + B)*196 + xy];
    }
    __syncthreads();
    for (int idx = t; idx < 196*16; idx += 256) {
        int xy = idx >> 4, h = idx & 15;
        float v = tile[h*197 + xy];
        g_PTe[((b*32 + B)*196 + xy)*16 + h] = v;
        g_PTm[((b*196 + xy)*32 + B)*16 + h] = v;
    }
}

__global__ __launch_bounds__(256) void prep_W_kernel(const float* __restrict__ W) {
    int o = blockIdx.x*256 + threadIdx.x;
    int c = o / 4608;
    int r = o - c*4608;
    int bkp = r >> 4, h = r & 15;
    int kq = bkp >> 5, B = bkp & 31;
    g_WTm[o] = W[((B*9 + kq)*32 + c)*16 + h];
}

__global__ __launch_bounds__(256) void prep_AW_kernel(const float* __restrict__ act) {
    int idx = blockIdx.x*256 + threadIdx.x;
    if (idx >= NB*WW*BKK) return;
    int b = idx / (WW*BKK);
    int r = idx % (WW*BKK);
    int ww = r / BKK, bkp = r % BKK;
    int kq = bkp >> 5, B = bkp & 31;
    int kx = kq / 3, ky = kq % 3;
    int wx = ww / 6, wy = ww % 6;
    g_AW[idx] = act[((b*32 + B)*14 + wx*2 + kx)*14 + wy*2 + ky];
}

// ---------------- warp multi-value reduction ---------------------------------
// Reduces v[0..15] across 32 lanes; lane l returns full-warp sum of value (l>>1).
__device__ __forceinline__ float reduce16(float v[16], int lane) {
#pragma unroll
    for (int k = 0; k < 8; k++) {
        float send = (lane & 16) ? v[k] : v[k + 8];
        float r = __shfl_xor_sync(0xffffffffu, send, 16);
        v[k] = ((lane & 16) ? v[k + 8] : v[k]) + r;
    }
#pragma unroll
    for (int k = 0; k < 4; k++) {
        float send = (lane & 8) ? v[k] : v[k + 4];
        float r = __shfl_xor_sync(0xffffffffu, send, 8);
        v[k] = ((lane & 8) ? v[k + 4] : v[k]) + r;
    }
#pragma unroll
    for (int k = 0; k < 2; k++) {
        float send = (lane & 4) ? v[k] : v[k + 2];
        float r = __shfl_xor_sync(0xffffffffu, send, 4);
        v[k] = ((lane & 4) ? v[k + 2] : v[k]) + r;
    }
    {
        float send = (lane & 2) ? v[0] : v[1];
        float r = __shfl_xor_sync(0xffffffffu, send, 2);
        v[0] = ((lane & 2) ? v[1] : v[0]) + r;
    }
    return v[0] + __shfl_xor_sync(0xffffffffu, v[0], 1);
}

// ---------------- M step ------------------------------------------------------
// Block = (ww, b); 288 threads = bkk' (warp=kq, lane=B); loop over all 32 c.
// Pose row stays in registers; per-c: load W row + R, votes in registers,
// shuffle-reduce; warp 0 finalizes mu/sigma/a.
__global__ __launch_bounds__(288, 3) void m_step_kernel(
    const float* __restrict__ beta_v, const float* __restrict__ beta_a,
    const float* __restrict__ lambda_, int first_iter, float* __restrict__ out) {
    const int ww = blockIdx.x, b = blockIdx.y;
    const int t = threadIdx.x;
    const int warp = t >> 5, lane = t & 31;      // kq, B
    const int wx = ww / 6, wy = ww % 6;
    const int x = wx*2 + warp/3, y = wy*2 + warp%3;

    __shared__ float smR[2][9*32];   // per-warp partials: slot lane<16->S1[h], >=16->S2[h]
    __shared__ float sm0[2][9];

    // persistent per-thread data
    float P[16];
    {
        const float4* pp = reinterpret_cast<const float4*>(
            &g_PTm[((b*196 + x*14 + y)*32 + lane)*16]);
        float4 p0 = pp[0], p1 = pp[1], p2 = pp[2], p3 = pp[3];
        P[0]=p0.x; P[1]=p0.y; P[2]=p0.z; P[3]=p0.w;
        P[4]=p1.x; P[5]=p1.y; P[6]=p1.z; P[7]=p1.w;
        P[8]=p2.x; P[9]=p2.y; P[10]=p2.z; P[11]=p2.w;
        P[12]=p3.x; P[13]=p3.y; P[14]=p3.z; P[15]=p3.w;
    }
    const float aw = g_AW[(b*WW + ww)*BKK + t];
    const float lam = lambda_[0];

    for (int cc = 0; cc < CCAPS; cc++) {
        const int buf = cc & 1;
        float rr = first_iter ? (1.0f/(float)CWW)
                              : g_RT[((size_t)b*CWW + cc*36 + ww)*BKK + t];
        float rw = rr * aw;

        // W row for (cc, bkk'=t)
        float V[16];
        {
            const float4* wp4 = reinterpret_cast<const float4*>(&g_WTm[(cc*BKK + t)*16]);
            float4 w0 = wp4[0], w1 = wp4[1], w2 = wp4[2], w3 = wp4[3];
            float Wr[16] = {w0.x,w0.y,w0.z,w0.w, w1.x,w1.y,w1.z,w1.w,
                            w2.x,w2.y,w2.z,w2.w, w3.x,w3.y,w3.z,w3.w};
#pragma unroll
            for (int i = 0; i < 4; i++)
#pragma unroll
                for (int j = 0; j < 4; j++)
                    V[i*4+j] = Wr[i*4+0]*P[j]   + Wr[i*4+1]*P[4+j]
                             + Wr[i*4+2]*P[8+j] + Wr[i*4+3]*P[12+j];
        }

        // S0 = sum rw over warp
        float s0 = rw;
#pragma unroll
        for (int o = 16; o > 0; o >>= 1) s0 += __shfl_xor_sync(0xffffffffu, s0, o);

        // S2 products first (V stays live), then S1 in-place over V
        float t1[16];
#pragma unroll
        for (int h = 0; h < 16; h++) t1[h] = rw * V[h] * V[h];
        float S2p = reduce16(t1, lane);
#pragma unroll
        for (int h = 0; h < 16; h++) V[h] = rw * V[h];
        float S1p = reduce16(V, lane);

        // even lanes hold S1[lane>>1], odd lanes S2[lane>>1]; slot index == lane mapping
        int hslot = (lane >> 1) + ((lane & 1) << 4);
        smR[buf][warp*32 + hslot] = (lane & 1) ? S2p : S1p;
        if (lane == 0) sm0[buf][warp] = s0;
        __syncthreads();

        if (warp == 0) {
            float acc = 0.f;
#pragma unroll
            for (int w2 = 0; w2 < 9; w2++) acc += smR[buf][w2*32 + lane];
            float S0 = 0.f;
#pragma unroll
            for (int w2 = 0; w2 < 9; w2++) S0 += sm0[buf][w2];
            float other = __shfl_xor_sync(0xffffffffu, acc, 16);
            // lanes<16: acc=S1[h], other=S2[h]
            float mu = acc / S0;
            float varr = fmaxf(other / S0 - mu * mu, 1e-30f);
            float sg = sqrtf(varr);
            float costp = logf(sg + EPSV);
            if (lane < 16) {
                int o = ((b*WW + ww)*CCAPS + cc)*16 + lane;
                g_mu[o]   = mu;
                g_isig[o] = 1.0f / sg;
                if (out) out[((b*CCAPS + cc)*WW + ww)*16 + lane] = mu;
            }
            float cs = costp;
            cs += __shfl_xor_sync(0xffffffffu, cs, 8);
            cs += __shfl_xor_sync(0xffffffffu, cs, 4);
            cs += __shfl_xor_sync(0xffffffffu, cs, 2);
            cs += __shfl_xor_sync(0xffffffffu, cs, 1);
            if (lane == 0) {
                float total = (cs + 16.0f * beta_v[cc]) * S0;
                float a = 1.0f / (1.0f + __expf(-lam * (beta_a[cc] - total)));
                g_a[(b*WW + ww)*CCAPS + cc] = a;
                if (out) out[NB*CCAPS*WW*16 + (b*CCAPS + cc)*WW + ww] = a;
            }
        }
        // double buffer: next iter writes buf^1; buf is rewritten only after
        // the next barrier, by which time warp 0 has consumed it.
    }
}

// ---------------- E step ------------------------------------------------------
__global__ __launch_bounds__(288) void e_step_kernel(const float* __restrict__ W) {
    int B = blockIdx.x, b = blockIdx.y;
    int t = threadIdx.x;
    int warp = t >> 5, lane = t & 31;   // warp = kq, lane = c
    int bkk_in  = B*9 + warp;
    int bkk_out = warp*32 + B;
    int kx = warp / 3, ky = warp % 3;

    __shared__ float psm [196*16];
    __shared__ float musm[6*32*17];
    __shared__ float issm[6*32*17];
    __shared__ float a_sm[6*32];

    for (int idx = t; idx < 3136; idx += 288)
        psm[idx] = g_PTe[(size_t)(b*32 + B)*3136 + idx];

    float Wreg[16];
    const float* wp = &W[(bkk_in*32 + lane)*16];
#pragma unroll
    for (int q = 0; q < 4; q++) {
        float4 f = *reinterpret_cast<const float4*>(wp + q*4);
        Wreg[q*4+0] = f.x; Wreg[q*4+1] = f.y;
        Wreg[q*4+2] = f.z; Wreg[q*4+3] = f.w;
    }

    float rs_local = 0.f;
    for (int tile = 0; tile < 6; tile++) {       // tile == wx
        __syncthreads();
        for (int idx = t; idx < 6*32*16; idx += 288) {
            int wl = idx >> 9;
            int c2 = (idx >> 4) & 31;
            int h2 = idx & 15;
            int go = ((b*WW + tile*6 + wl)*CCAPS + c2)*16 + h2;
            musm[(wl*32 + c2)*17 + h2] = g_mu[go];
            issm[(wl*32 + c2)*17 + h2] = g_isig[go];
        }
        for (int idx = t; idx < 192; idx += 288) {
            int wl = idx >> 5, c2 = idx & 31;
            a_sm[idx] = g_a[(b*WW + tile*6 + wl)*CCAPS + c2];
        }
        __syncthreads();

        for (int wl = 0; wl < 6; wl++) {         // wl == wy
            int ww = tile*6 + wl;
            const float* pp = &psm[((2*tile + kx)*14 + 2*wl + ky)*16];
            float P[16];
#pragma unroll
            for (int q = 0; q < 16; q++) P[q] = pp[q];
            float V[16];
#pragma unroll
            for (int i = 0; i < 4; i++)
#pragma unroll
                for (int jj = 0; jj < 4; jj++)
                    V[i*4+jj] = Wreg[i*4+0]*P[jj]   + Wreg[i*4+1]*P[4+jj]
                              + Wreg[i*4+2]*P[8+jj] + Wreg[i*4+3]*P[12+jj];
            int base = (wl*32 + lane)*17;
            float p = 0.f;
#pragma unroll
            for (int h = 0; h < 16; h++) {
                float m  = musm[base + h];
                float is = issm[base + h];
                float z  = (V[h] + EPSV - m) * is;
                p += is * RSQRT2PI * __expf(-0.5f * z * z);
            }
            float ap = a_sm[wl*32 + lane] * p;
            g_AP[((size_t)(b*BKK + bkk_out)*WW + ww)*CCAPS + lane] = ap;
            rs_local += ap;
        }
    }
#pragma unroll
    for (int o = 16; o > 0; o >>= 1)
        rs_local += __shfl_xor_sync(0xffffffffu, rs_local, o);
    if (lane == 0) g_rowsum[b*BKK + bkk_out] = rs_local;
}

// ---------------- normalize + transpose --------------------------------------
__global__ __launch_bounds__(256) void norm_kernel() {
    int ww = blockIdx.x, bt = blockIdx.y, b = blockIdx.z;
    int t = threadIdx.x;
    int tx = t & 31, ty = t >> 5;
    __shared__ float tile[32*33];
    __shared__ float rs[32];
    if (t < 32) rs[t] = g_rowsum[b*BKK + bt*32 + t];
    __syncthreads();
#pragma unroll
    for (int r = 0; r < 4; r++) {
        int bl = ty + r*8;
        float v = g_AP[((size_t)(b*BKK + bt*32 + bl)*WW + ww)*CCAPS + tx];
        tile[bl*33 + tx] = v / rs[bl] + EPSV;
    }
    __syncthreads();
#pragma unroll
    for (int r = 0; r < 4; r++) {
        int cc = ty + r*8;
        g_RT[((size_t)b*CWW + cc*36 + ww)*BKK + bt*32 + tx] = tile[tx*33 + cc];
    }
}

// ---------------- launch ------------------------------------------------------
extern "C" void kernel_launch(void* const* d_in, const int* in_sizes, int n_in,
                              void* d_out, int out_size) {
    const float* poses  = (const float*)d_in[0];
    const float* act    = (const float*)d_in[1];
    const float* W      = (const float*)d_in[2];
    const float* beta_v = (const float*)d_in[3];
    const float* beta_a = (const float*)d_in[4];
    const float* lam    = (const float*)d_in[5];
    float* out = (float*)d_out;

    prep_pose_kernel<<<dim3(32,16), 256>>>(poses);
    prep_W_kernel<<<576, 256>>>(W);
    prep_AW_kernel<<<(NB*WW*BKK + 255)/256, 256>>>(act);

    for (int it = 0; it < 3; it++) {
        m_step_kernel<<<dim3(36,16), 288>>>(beta_v, beta_a, lam,
                                            it == 0 ? 1 : 0,
                                            it == 2 ? out : (float*)nullptr);
        if (it < 2) {
            e_step_kernel<<<dim3(32,16), 288>>>(W);
            norm_kernel<<<dim3(36,9,16), 256>>>();
        }
    }
}

// round 5
// speedup vs baseline: 2.5852x; 1.3811x over previous
#include <cuda_runtime.h>
#include <math.h>

#define BCAPS 32
#define CCAPS 32
#define HH    16
#define WW    36
#define BKK   288
#define CWW   1152
#define NB    16
#define EPSV  1e-10f
#define RSQRT2PI 0.3989422804014327f
#define K1EXP 0.84932180028801904f   /* sqrt(0.5*log2(e)) */

// internal bkk ordering: bkk' = kq*32 + B

// ---------------- scratch ----------------------------------------------------
__device__ float  g_PTm[NB*196*BCAPS*HH];   // pose [b][xy][B][hh]
__device__ float  g_PTe[NB*BCAPS*196*HH];   // pose [b][B][xy][hh]
__device__ float  g_WTm[CCAPS*BKK*HH];      // W    [c][bkk'][hh]
__device__ float  g_AW [NB*WW*BKK];         // act window [b][ww][bkk']
__device__ float  g_RT [NB*CWW*BKK];        // R^T  [b][cww][bkk']
__device__ float  g_AP [NB*BKK*WW*CCAPS];   // a*p  [b][bkk'][ww][c]
__device__ float  g_rowsum[NB*BKK];
__device__ float4 g_EP [NB*WW*HH*CCAPS];    // (A, B, isC, _) [b][ww][h][c]
__device__ float  g_a  [NB*WW*CCAPS];

__device__ __forceinline__ float ex2f(float x) {
    float r; asm("ex2.approx.f32 %0, %1;" : "=f"(r) : "f"(x)); return r;
}

// ---------------- prep kernels -----------------------------------------------
__global__ __launch_bounds__(256) void prep_pose_kernel(const float* __restrict__ poses) {
    int B = blockIdx.x, b = blockIdx.y, t = threadIdx.x;
    __shared__ float tile[16*197];
    for (int idx = t; idx < 16*196; idx += 256) {
        int h = idx / 196, xy = idx % 196;
        tile[h*197 + xy] = poses[(b*512 + h*32 + B)*196 + xy];
    }
    __syncthreads();
    for (int idx = t; idx < 196*16; idx += 256) {
        int xy = idx >> 4, h = idx & 15;
        float v = tile[h*197 + xy];
        g_PTe[((b*32 + B)*196 + xy)*16 + h] = v;
        g_PTm[((b*196 + xy)*32 + B)*16 + h] = v;
    }
}

__global__ __launch_bounds__(256) void prep_W_kernel(const float* __restrict__ W) {
    int o = blockIdx.x*256 + threadIdx.x;
    int c = o / 4608;
    int r = o - c*4608;
    int bkp = r >> 4, h = r & 15;
    int kq = bkp >> 5, B = bkp & 31;
    g_WTm[o] = W[((B*9 + kq)*32 + c)*16 + h];
}

__global__ __launch_bounds__(256) void prep_AW_kernel(const float* __restrict__ act) {
    int idx = blockIdx.x*256 + threadIdx.x;
    if (idx >= NB*WW*BKK) return;
    int b = idx / (WW*BKK);
    int r = idx % (WW*BKK);
    int ww = r / BKK, bkp = r % BKK;
    int kq = bkp >> 5, B = bkp & 31;
    g_AW[idx] = act[((b*32 + B)*14 + (ww/6)*2 + kq/3)*14 + (ww%6)*2 + kq%3];
}

// ---------------- warp multi-value reduction ---------------------------------
// lane l ends with the full-warp sum of value index (l>>1).
__device__ __forceinline__ float reduce16(float v[16], int lane) {
#pragma unroll
    for (int k = 0; k < 8; k++) {
        float send = (lane & 16) ? v[k] : v[k + 8];
        float r = __shfl_xor_sync(0xffffffffu, send, 16);
        v[k] = ((lane & 16) ? v[k + 8] : v[k]) + r;
    }
#pragma unroll
    for (int k = 0; k < 4; k++) {
        float send = (lane & 8) ? v[k] : v[k + 4];
        float r = __shfl_xor_sync(0xffffffffu, send, 8);
        v[k] = ((lane & 8) ? v[k + 4] : v[k]) + r;
    }
#pragma unroll
    for (int k = 0; k < 2; k++) {
        float send = (lane & 4) ? v[k] : v[k + 2];
        float r = __shfl_xor_sync(0xffffffffu, send, 4);
        v[k] = ((lane & 4) ? v[k + 2] : v[k]) + r;
    }
    {
        float send = (lane & 2) ? v[0] : v[1];
        float r = __shfl_xor_sync(0xffffffffu, send, 2);
        v[0] = ((lane & 2) ? v[1] : v[0]) + r;
    }
    return v[0] + __shfl_xor_sync(0xffffffffu, v[0], 1);
}

// ---------------- M step ------------------------------------------------------
// Block = (ww, b, cg): 8 c per block, 288 threads = bkk' (warp=kq, lane=B).
// No barrier inside the c-loop; one sync + parallel finalize.
__global__ __launch_bounds__(288, 3) void m_step_kernel(
    const float* __restrict__ beta_v, const float* __restrict__ beta_a,
    const float* __restrict__ lambda_, int first_iter, float* __restrict__ out) {
    const int ww = blockIdx.x, b = blockIdx.y, c0 = blockIdx.z * 8;
    const int t = threadIdx.x;
    const int warp = t >> 5, lane = t & 31;
    const int x = (ww/6)*2 + warp/3, y = (ww%6)*2 + warp%3;

    __shared__ float smP[8*9*34];   // [c][warp][slot0..31 +2 pad]
    __shared__ float smS0[8*9];
    __shared__ float cost_sm[128];

    float P[16];
    {
        const float4* pp = reinterpret_cast<const float4*>(
            &g_PTm[((b*196 + x*14 + y)*32 + lane)*16]);
        float4 p0 = pp[0], p1 = pp[1], p2 = pp[2], p3 = pp[3];
        P[0]=p0.x; P[1]=p0.y; P[2]=p0.z; P[3]=p0.w;
        P[4]=p1.x; P[5]=p1.y; P[6]=p1.z; P[7]=p1.w;
        P[8]=p2.x; P[9]=p2.y; P[10]=p2.z; P[11]=p2.w;
        P[12]=p3.x; P[13]=p3.y; P[14]=p3.z; P[15]=p3.w;
    }
    const float aw = g_AW[(b*WW + ww)*BKK + t];
    const int hslot = (lane >> 1) + ((lane & 1) << 4);

#pragma unroll 2
    for (int cc = 0; cc < 8; cc++) {
        const int c = c0 + cc;
        float rr = first_iter ? (1.0f/(float)CWW)
                              : g_RT[((size_t)b*CWW + c*36 + ww)*BKK + t];
        float rw = rr * aw;

        float V[16];
        {
            const float4* wp4 = reinterpret_cast<const float4*>(&g_WTm[(c*BKK + t)*16]);
            float4 w0 = wp4[0], w1 = wp4[1], w2 = wp4[2], w3 = wp4[3];
            float Wr[16] = {w0.x,w0.y,w0.z,w0.w, w1.x,w1.y,w1.z,w1.w,
                            w2.x,w2.y,w2.z,w2.w, w3.x,w3.y,w3.z,w3.w};
#pragma unroll
            for (int i = 0; i < 4; i++)
#pragma unroll
                for (int j = 0; j < 4; j++)
                    V[i*4+j] = Wr[i*4+0]*P[j]   + Wr[i*4+1]*P[4+j]
                             + Wr[i*4+2]*P[8+j] + Wr[i*4+3]*P[12+j];
        }

        float s0 = rw;
#pragma unroll
        for (int o = 16; o > 0; o >>= 1) s0 += __shfl_xor_sync(0xffffffffu, s0, o);

        float t1[16];
#pragma unroll
        for (int h = 0; h < 16; h++) t1[h] = rw * V[h] * V[h];
        float S2p = reduce16(t1, lane);
#pragma unroll
        for (int h = 0; h < 16; h++) V[h] = rw * V[h];
        float S1p = reduce16(V, lane);

        smP[(cc*9 + warp)*34 + hslot] = (lane & 1) ? S2p : S1p;
        if (lane == 0) smS0[cc*9 + warp] = s0;
    }
    __syncthreads();

    // finalize A: thread t<128 owns (c = t>>4, h = t&15)
    if (t < 128) {
        int cc = t >> 4, h = t & 15;
        const float* base = &smP[cc*9*34];
        float S1 = 0.f, S2 = 0.f, S0 = 0.f;
#pragma unroll
        for (int w2 = 0; w2 < 9; w2++) {
            S1 += base[w2*34 + h];
            S2 += base[w2*34 + 16 + h];
            S0 += smS0[cc*9 + w2];
        }
        float mu = S1 / S0;
        float varr = fmaxf(S2 / S0 - mu*mu, 1e-30f);
        float sg = sqrtf(varr);
        float is = 1.0f / sg;
        cost_sm[t] = logf(sg + EPSV);
        float A = is * K1EXP;
        float4 e4;
        e4.x = A;
        e4.y = -(mu - EPSV) * A;
        e4.z = is * RSQRT2PI;
        e4.w = 0.f;
        g_EP[((b*WW + ww)*HH + h)*CCAPS + c0 + cc] = e4;
        if (out) out[((b*CCAPS + c0 + cc)*WW + ww)*HH + h] = mu;
    }
    __syncthreads();

    // finalize B: thread t<8 owns c
    if (t < 8) {
        int c = c0 + t;
        float cs = 0.f;
#pragma unroll
        for (int h = 0; h < 16; h++) cs += cost_sm[t*16 + h];
        float S0 = 0.f;
#pragma unroll
        for (int w2 = 0; w2 < 9; w2++) S0 += smS0[t*9 + w2];
        float total = (cs + 16.0f * beta_v[c]) * S0;
        float lam = lambda_[0];
        float a = 1.0f / (1.0f + __expf(-lam * (beta_a[c] - total)));
        g_a[(b*WW + ww)*CCAPS + c] = a;
        if (out) out[NB*CCAPS*WW*HH + (b*CCAPS + c)*WW + ww] = a;
    }
}

// ---------------- E step ------------------------------------------------------
// Block = (Bpair, b): 576 threads, 18 warps; warps 0-8 -> B0, 9-17 -> B1.
// warp%9 = kq, lane = c. Dynamic smem: psm[2*3136] | esm[3072 float4] | a_sm[192]
__global__ __launch_bounds__(576, 2) void e_step_kernel(const float* __restrict__ W) {
    int Bp = blockIdx.x, b = blockIdx.y;
    int t = threadIdx.x;
    int warp = t >> 5, lane = t & 31;
    int wg = warp >= 9;
    int kq = warp - wg*9;
    int B  = Bp*2 + wg;
    int bkk_in  = B*9 + kq;
    int bkk_out = kq*32 + B;
    int kx = kq / 3, ky = kq % 3;

    extern __shared__ float sm[];
    float*  psm  = sm;                               // 6272 floats
    float4* esm  = reinterpret_cast<float4*>(sm + 6272);  // 3072 float4
    float*  a_sm = sm + 6272 + 3072*4;               // 192 floats

    for (int idx = t; idx < 3136; idx += 576) {
        psm[idx]        = g_PTe[(size_t)(b*32 + Bp*2    )*3136 + idx];
        psm[3136 + idx] = g_PTe[(size_t)(b*32 + Bp*2 + 1)*3136 + idx];
    }

    float Wreg[16];
    {
        const float* wp = &W[(bkk_in*32 + lane)*16];
#pragma unroll
        for (int q = 0; q < 4; q++) {
            float4 f = *reinterpret_cast<const float4*>(wp + q*4);
            Wreg[q*4+0] = f.x; Wreg[q*4+1] = f.y;
            Wreg[q*4+2] = f.z; Wreg[q*4+3] = f.w;
        }
    }

    float rs_local = 0.f;
    for (int tile = 0; tile < 6; tile++) {       // tile == wx
        __syncthreads();
        const float4* src = &g_EP[(size_t)(b*WW + tile*6)*HH*CCAPS];
        for (int idx = t; idx < 3072; idx += 576) esm[idx] = src[idx];
        for (int idx = t; idx < 192; idx += 576)
            a_sm[idx] = g_a[(b*WW + tile*6)*CCAPS + idx];
        __syncthreads();

#pragma unroll
        for (int wl = 0; wl < 6; wl++) {         // wl == wy
            const float* pp = &psm[wg*3136 + ((2*tile + kx)*14 + 2*wl + ky)*16];
            float P[16];
#pragma unroll
            for (int q = 0; q < 16; q++) P[q] = pp[q];
            float V[16];
#pragma unroll
            for (int i = 0; i < 4; i++)
#pragma unroll
                for (int jj = 0; jj < 4; jj++)
                    V[i*4+jj] = Wreg[i*4+0]*P[jj]   + Wreg[i*4+1]*P[4+jj]
                              + Wreg[i*4+2]*P[8+jj] + Wreg[i*4+3]*P[12+jj];
            const float4* ep = &esm[(wl*16)*32 + lane];
            float p = 0.f;
#pragma unroll
            for (int h = 0; h < 16; h++) {
                float4 e4 = ep[h*32];
                float u = fmaf(V[h], e4.x, e4.y);
                float e = ex2f(-u*u);
                p = fmaf(e4.z, e, p);
            }
            float ap = a_sm[wl*32 + lane] * p;
            g_AP[((size_t)(b*BKK + bkk_out)*WW + tile*6 + wl)*CCAPS + lane] = ap;
            rs_local += ap;
        }
    }
#pragma unroll
    for (int o = 16; o > 0; o >>= 1)
        rs_local += __shfl_xor_sync(0xffffffffu, rs_local, o);
    if (lane == 0) g_rowsum[b*BKK + bkk_out] = rs_local;
}

// ---------------- normalize + transpose --------------------------------------
__global__ __launch_bounds__(256) void norm_kernel() {
    int ww = blockIdx.x, bt = blockIdx.y, b = blockIdx.z;
    int t = threadIdx.x;
    int tx = t & 31, ty = t >> 5;
    __shared__ float tile[32*33];
    __shared__ float rs[32];
    if (t < 32) rs[t] = g_rowsum[b*BKK + bt*32 + t];
    __syncthreads();
#pragma unroll
    for (int r = 0; r < 4; r++) {
        int bl = ty + r*8;
        float v = g_AP[((size_t)(b*BKK + bt*32 + bl)*WW + ww)*CCAPS + tx];
        tile[bl*33 + tx] = v / rs[bl] + EPSV;
    }
    __syncthreads();
#pragma unroll
    for (int r = 0; r < 4; r++) {
        int cc = ty + r*8;
        g_RT[((size_t)b*CWW + cc*36 + ww)*BKK + bt*32 + tx] = tile[tx*33 + cc];
    }
}

// ---------------- launch ------------------------------------------------------
extern "C" void kernel_launch(void* const* d_in, const int* in_sizes, int n_in,
                              void* d_out, int out_size) {
    const float* poses  = (const float*)d_in[0];
    const float* act    = (const float*)d_in[1];
    const float* W      = (const float*)d_in[2];
    const float* beta_v = (const float*)d_in[3];
    const float* beta_a = (const float*)d_in[4];
    const float* lam    = (const float*)d_in[5];
    float* out = (float*)d_out;

    const int SMEM_E = (6272 + 192)*4 + 3072*16;   // 75008 bytes
    static int attr_done = 0;
    if (!attr_done) {
        cudaFuncSetAttribute(e_step_kernel,
                             cudaFuncAttributeMaxDynamicSharedMemorySize, SMEM_E);
        attr_done = 1;
    }

    prep_pose_kernel<<<dim3(32,16), 256>>>(poses);
    prep_W_kernel<<<576, 256>>>(W);
    prep_AW_kernel<<<(NB*WW*BKK + 255)/256, 256>>>(act);

    for (int it = 0; it < 3; it++) {
        m_step_kernel<<<dim3(36,16,4), 288>>>(beta_v, beta_a, lam,
                                              it == 0 ? 1 : 0,
                                              it == 2 ? out : (float*)nullptr);
        if (it < 2) {
            e_step_kernel<<<dim3(16,16), 576, SMEM_E>>>(W);
            norm_kernel<<<dim3(36,9,16), 256>>>();
        }
    }
}

// round 7
// speedup vs baseline: 2.7400x; 1.0599x over previous
#include <cuda_runtime.h>
#include <math.h>

#define BCAPS 32
#define CCAPS 32
#define HH    16
#define WW    36
#define BKK   288
#define CWW   1152
#define NB    16
#define EPSV  1e-10f
#define RSQRT2PI 0.3989422804014327f
#define K1EXP 0.84932180028801904f   /* sqrt(0.5*log2(e)) */

// internal bkk ordering: bkk' = kq*32 + B

// ---------------- scratch ----------------------------------------------------
__device__ float  g_PTm[NB*196*BCAPS*HH];   // pose [b][xy][B][hh]
__device__ float  g_PTe[NB*BCAPS*196*HH];   // pose [b][B][xy][hh]
__device__ float  g_WTm[CCAPS*BKK*HH];      // W    [c][bkk'][hh]
__device__ float  g_AW [NB*WW*BKK];         // act window [b][ww][bkk']
__device__ float  g_RT [NB*CWW*BKK];        // R^T  [b][cww][bkk']
__device__ float  g_AP [NB*BKK*WW*CCAPS];   // a*p  [b][bkk'][ww][c]
__device__ float  g_rowsum[NB*BKK];
__device__ float4 g_EP [NB*WW*HH*CCAPS];    // (A, B, isC, _) [b][ww][h][c]
__device__ float  g_a  [NB*WW*CCAPS];

__device__ __forceinline__ float ex2f(float x) {
    float r; asm("ex2.approx.f32 %0, %1;" : "=f"(r) : "f"(x)); return r;
}

// ---------------- prep kernels -----------------------------------------------
__global__ __launch_bounds__(256) void prep_pose_kernel(const float* __restrict__ poses) {
    int B = blockIdx.x, b = blockIdx.y, t = threadIdx.x;
    __shared__ float tile[16*197];
    for (int idx = t; idx < 16*196; idx += 256) {
        int h = idx / 196, xy = idx % 196;
        tile[h*197 + xy] = poses[(b*512 + h*32 + B)*196 + xy];
    }
    __syncthreads();
    for (int idx = t; idx < 196*16; idx += 256) {
        int xy = idx >> 4, h = idx & 15;
        float v = tile[h*197 + xy];
        g_PTe[((b*32 + B)*196 + xy)*16 + h] = v;
        g_PTm[((b*196 + xy)*32 + B)*16 + h] = v;
    }
}

__global__ __launch_bounds__(256) void prep_W_kernel(const float* __restrict__ W) {
    int o = blockIdx.x*256 + threadIdx.x;
    int c = o / 4608;
    int r = o - c*4608;
    int bkp = r >> 4, h = r & 15;
    int kq = bkp >> 5, B = bkp & 31;
    g_WTm[o] = W[((B*9 + kq)*32 + c)*16 + h];
}

__global__ __launch_bounds__(256) void prep_AW_kernel(const float* __restrict__ act) {
    int idx = blockIdx.x*256 + threadIdx.x;
    if (idx >= NB*WW*BKK) return;
    int b = idx / (WW*BKK);
    int r = idx % (WW*BKK);
    int ww = r / BKK, bkp = r % BKK;
    int kq = bkp >> 5, B = bkp & 31;
    g_AW[idx] = act[((b*32 + B)*14 + (ww/6)*2 + kq/3)*14 + (ww%6)*2 + kq%3];
}

// ---------------- warp multi-value reduction ---------------------------------
// lane l ends with the full-warp sum of value index (l>>1).
__device__ __forceinline__ float reduce16(float v[16], int lane) {
#pragma unroll
    for (int k = 0; k < 8; k++) {
        float send = (lane & 16) ? v[k] : v[k + 8];
        float r = __shfl_xor_sync(0xffffffffu, send, 16);
        v[k] = ((lane & 16) ? v[k + 8] : v[k]) + r;
    }
#pragma unroll
    for (int k = 0; k < 4; k++) {
        float send = (lane & 8) ? v[k] : v[k + 4];
        float r = __shfl_xor_sync(0xffffffffu, send, 8);
        v[k] = ((lane & 8) ? v[k + 4] : v[k]) + r;
    }
#pragma unroll
    for (int k = 0; k < 2; k++) {
        float send = (lane & 4) ? v[k] : v[k + 2];
        float r = __shfl_xor_sync(0xffffffffu, send, 4);
        v[k] = ((lane & 4) ? v[k + 2] : v[k]) + r;
    }
    {
        float send = (lane & 2) ? v[0] : v[1];
        float r = __shfl_xor_sync(0xffffffffu, send, 2);
        v[0] = ((lane & 2) ? v[1] : v[0]) + r;
    }
    return v[0] + __shfl_xor_sync(0xffffffffu, v[0], 1);
}

__device__ __forceinline__ void load16(const float* __restrict__ src, float d[16]) {
    const float4* p4 = reinterpret_cast<const float4*>(src);
    float4 a0 = p4[0], a1 = p4[1], a2 = p4[2], a3 = p4[3];
    d[0]=a0.x; d[1]=a0.y; d[2]=a0.z; d[3]=a0.w;
    d[4]=a1.x; d[5]=a1.y; d[6]=a1.z; d[7]=a1.w;
    d[8]=a2.x; d[9]=a2.y; d[10]=a2.z; d[11]=a2.w;
    d[12]=a3.x; d[13]=a3.y; d[14]=a3.z; d[15]=a3.w;
}

__device__ __forceinline__ void votes4x4(const float Wr[16], const float P[16], float V[16]) {
#pragma unroll
    for (int i = 0; i < 4; i++)
#pragma unroll
        for (int j = 0; j < 4; j++)
            V[i*4+j] = Wr[i*4+0]*P[j]   + Wr[i*4+1]*P[4+j]
                     + Wr[i*4+2]*P[8+j] + Wr[i*4+3]*P[12+j];
}

// ---------------- M step ------------------------------------------------------
// Block = (ww, b, cg): 8 c per block, 160 threads = 5 warps.
// Warps 0-3 own kq pairs {0,1},{2,3},{4,5},{6,7}; warp 4 owns kq 8.
// Each thread accumulates 2 bkk before the shuffle tree.
__global__ __launch_bounds__(160, 4) void m_step_kernel(
    const float* __restrict__ beta_v, const float* __restrict__ beta_a,
    const float* __restrict__ lambda_, int first_iter, float* __restrict__ out) {
    const int ww = blockIdx.x, b = blockIdx.y, c0 = blockIdx.z * 8;
    const int t = threadIdx.x;
    const int warp = t >> 5, lane = t & 31;
    const int kqa = warp*2, kqb = warp*2 + 1;
    const bool has_b = (warp < 4);
    const int wx = ww/6, wy = ww%6;
    const int xa = wx*2 + kqa/3, ya = wy*2 + kqa%3;
    const int xb = wx*2 + (has_b ? kqb/3 : 0), yb = wy*2 + (has_b ? kqb%3 : 0);

    __shared__ float smP[8*5*34];
    __shared__ float smS0[8*5];
    __shared__ float cost_sm[128];

    float Pa[16], Pb[16];
    load16(&g_PTm[((b*196 + xa*14 + ya)*32 + lane)*16], Pa);
    if (has_b) load16(&g_PTm[((b*196 + xb*14 + yb)*32 + lane)*16], Pb);
    const float awa = g_AW[(b*WW + ww)*BKK + kqa*32 + lane];
    const float awb = has_b ? g_AW[(b*WW + ww)*BKK + kqb*32 + lane] : 0.f;
    const int hslot = (lane >> 1) + ((lane & 1) << 4);
    const size_t rbase = (size_t)b*CWW*BKK;

    for (int cc = 0; cc < 8; cc++) {
        const int c = c0 + cc;
        float rwa = (first_iter ? (1.0f/(float)CWW)
                                : g_RT[rbase + (size_t)(c*36 + ww)*BKK + kqa*32 + lane]) * awa;
        float rwb = 0.f;
        if (has_b)
            rwb = (first_iter ? (1.0f/(float)CWW)
                              : g_RT[rbase + (size_t)(c*36 + ww)*BKK + kqb*32 + lane]) * awb;

        float Wr[16], V[16], s1[16], t2[16];
        load16(&g_WTm[(c*BKK + kqa*32 + lane)*16], Wr);
        votes4x4(Wr, Pa, V);
#pragma unroll
        for (int h = 0; h < 16; h++) {
            float rv = rwa * V[h];
            s1[h] = rv;
            t2[h] = rv * V[h];
        }
        if (has_b) {
            load16(&g_WTm[(c*BKK + kqb*32 + lane)*16], Wr);
            votes4x4(Wr, Pb, V);
#pragma unroll
            for (int h = 0; h < 16; h++) {
                float rv = rwb * V[h];
                s1[h] += rv;
                t2[h] += rv * V[h];
            }
        }

        float s0 = rwa + rwb;
#pragma unroll
        for (int o = 16; o > 0; o >>= 1) s0 += __shfl_xor_sync(0xffffffffu, s0, o);

        float S2p = reduce16(t2, lane);
        float S1p = reduce16(s1, lane);

        smP[(cc*5 + warp)*34 + hslot] = (lane & 1) ? S2p : S1p;
        if (lane == 0) smS0[cc*5 + warp] = s0;
    }
    __syncthreads();

    // finalize A: thread t<128 owns (c = t>>4, h = t&15)
    if (t < 128) {
        int cc = t >> 4, h = t & 15;
        const float* base = &smP[cc*5*34];
        float S1 = 0.f, S2 = 0.f, S0 = 0.f;
#pragma unroll
        for (int w2 = 0; w2 < 5; w2++) {
            S1 += base[w2*34 + h];
            S2 += base[w2*34 + 16 + h];
            S0 += smS0[cc*5 + w2];
        }
        float mu = S1 / S0;
        float varr = fmaxf(S2 / S0 - mu*mu, 1e-30f);
        float sg = sqrtf(varr);
        float is = 1.0f / sg;
        cost_sm[t] = logf(sg + EPSV);
        float A = is * K1EXP;
        float4 e4;
        e4.x = A;
        e4.y = -(mu - EPSV) * A;
        e4.z = is * RSQRT2PI;
        e4.w = 0.f;
        g_EP[((b*WW + ww)*HH + h)*CCAPS + c0 + cc] = e4;
        if (out) out[((b*CCAPS + c0 + cc)*WW + ww)*HH + h] = mu;
    }
    __syncthreads();

    // finalize B: thread t<8 owns c
    if (t < 8) {
        int c = c0 + t;
        float cs = 0.f;
#pragma unroll
        for (int h = 0; h < 16; h++) cs += cost_sm[t*16 + h];
        float S0 = 0.f;
#pragma unroll
        for (int w2 = 0; w2 < 5; w2++) S0 += smS0[t*5 + w2];
        float total = (cs + 16.0f * beta_v[c]) * S0;
        float lam = lambda_[0];
        float a = 1.0f / (1.0f + __expf(-lam * (beta_a[c] - total)));
        g_a[(b*WW + ww)*CCAPS + c] = a;
        if (out) out[NB*CCAPS*WW*HH + (b*CCAPS + c)*WW + ww] = a;
    }
}

// ---------------- E step ------------------------------------------------------
// Block = (Bpair, b): 288 threads, 9 warps = kq; each thread handles BOTH B of
// the pair (e4 float4 read once, used twice). lane = c.
__global__ __launch_bounds__(288, 2) void e_step_kernel(const float* __restrict__ W) {
    int Bp = blockIdx.x, b = blockIdx.y;
    int t = threadIdx.x;
    int warp = t >> 5, lane = t & 31;   // kq, c
    int kq = warp;
    int B0 = Bp*2, B1 = Bp*2 + 1;
    int bkk_out0 = kq*32 + B0;
    int bkk_out1 = kq*32 + B1;
    int kx = kq / 3, ky = kq % 3;

    extern __shared__ float sm[];
    float*  psm  = sm;                               // 2*3136 floats
    float4* esm  = reinterpret_cast<float4*>(sm + 6272);  // 3072 float4
    float*  a_sm = sm + 6272 + 3072*4;               // 192 floats

    for (int idx = t; idx < 3136; idx += 288) {
        psm[idx]        = g_PTe[(size_t)(b*32 + B0)*3136 + idx];
        psm[3136 + idx] = g_PTe[(size_t)(b*32 + B1)*3136 + idx];
    }

    float W0[16], W1[16];
    load16(&W[((B0*9 + kq)*32 + lane)*16], W0);
    load16(&W[((B1*9 + kq)*32 + lane)*16], W1);

    float rs0 = 0.f, rs1 = 0.f;
    for (int tile = 0; tile < 6; tile++) {       // tile == wx
        __syncthreads();
        const float4* src = &g_EP[(size_t)(b*WW + tile*6)*HH*CCAPS];
        for (int idx = t; idx < 3072; idx += 288) esm[idx] = src[idx];
        for (int idx = t; idx < 192; idx += 288)
            a_sm[idx] = g_a[(b*WW + tile*6)*CCAPS + idx];
        __syncthreads();

#pragma unroll
        for (int wl = 0; wl < 6; wl++) {         // wl == wy
            const float* pp = &psm[((2*tile + kx)*14 + 2*wl + ky)*16];
            float P[16], V0[16], V1[16];
#pragma unroll
            for (int q = 0; q < 16; q++) P[q] = pp[q];
            votes4x4(W0, P, V0);
#pragma unroll
            for (int q = 0; q < 16; q++) P[q] = pp[3136 + q];
            votes4x4(W1, P, V1);

            const float4* ep = &esm[(wl*16)*32 + lane];
            float p0 = 0.f, p1 = 0.f;
#pragma unroll
            for (int h = 0; h < 16; h++) {
                float4 e4 = ep[h*32];
                float u0 = fmaf(V0[h], e4.x, e4.y);
                float u1 = fmaf(V1[h], e4.x, e4.y);
                p0 = fmaf(e4.z, ex2f(-u0*u0), p0);
                p1 = fmaf(e4.z, ex2f(-u1*u1), p1);
            }
            float av = a_sm[wl*32 + lane];
            float ap0 = av * p0;
            float ap1 = av * p1;
            g_AP[((size_t)(b*BKK + bkk_out0)*WW + tile*6 + wl)*CCAPS + lane] = ap0;
            g_AP[((size_t)(b*BKK + bkk_out1)*WW + tile*6 + wl)*CCAPS + lane] = ap1;
            rs0 += ap0;
            rs1 += ap1;
        }
    }
#pragma unroll
    for (int o = 16; o > 0; o >>= 1) {
        rs0 += __shfl_xor_sync(0xffffffffu, rs0, o);
        rs1 += __shfl_xor_sync(0xffffffffu, rs1, o);
    }
    if (lane == 0) {
        g_rowsum[b*BKK + bkk_out0] = rs0;
        g_rowsum[b*BKK + bkk_out1] = rs1;
    }
}

// ---------------- normalize + transpose --------------------------------------
__global__ __launch_bounds__(256) void norm_kernel() {
    int ww = blockIdx.x, bt = blockIdx.y, b = blockIdx.z;
    int t = threadIdx.x;
    int tx = t & 31, ty = t >> 5;
    __shared__ float tile[32*33];
    __shared__ float rs[32];
    if (t < 32) rs[t] = g_rowsum[b*BKK + bt*32 + t];
    __syncthreads();
#pragma unroll
    for (int r = 0; r < 4; r++) {
        int bl = ty + r*8;
        float v = g_AP[((size_t)(b*BKK + bt*32 + bl)*WW + ww)*CCAPS + tx];
        tile[bl*33 + tx] = v / rs[bl] + EPSV;
    }
    __syncthreads();
#pragma unroll
    for (int r = 0; r < 4; r++) {
        int cc = ty + r*8;
        g_RT[((size_t)b*CWW + cc*36 + ww)*BKK + bt*32 + tx] = tile[tx*33 + cc];
    }
}

// ---------------- launch ------------------------------------------------------
extern "C" void kernel_launch(void* const* d_in, const int* in_sizes, int n_in,
                              void* d_out, int out_size) {
    const float* poses  = (const float*)d_in[0];
    const float* act    = (const float*)d_in[1];
    const float* W      = (const float*)d_in[2];
    const float* beta_v = (const float*)d_in[3];
    const float* beta_a = (const float*)d_in[4];
    const float* lam    = (const float*)d_in[5];
    float* out = (float*)d_out;

    const int SMEM_E = (6272 + 192)*4 + 3072*16;   // 75008 bytes
    static int attr_done = 0;
    if (!attr_done) {
        cudaFuncSetAttribute(e_step_kernel,
                             cudaFuncAttributeMaxDynamicSharedMemorySize, SMEM_E);
        attr_done = 1;
    }

    prep_pose_kernel<<<dim3(32,16), 256>>>(poses);
    prep_W_kernel<<<576, 256>>>(W);
    prep_AW_kernel<<<(NB*WW*BKK + 255)/256, 256>>>(act);

    for (int it = 0; it < 3; it++) {
        m_step_kernel<<<dim3(36,16,4), 160>>>(beta_v, beta_a, lam,
                                              it == 0 ? 1 : 0,
                                              it == 2 ? out : (float*)nullptr);
        if (it < 2) {
            e_step_kernel<<<dim3(16,16), 288, SMEM_E>>>(W);
            norm_kernel<<<dim3(36,9,16), 256>>>();
        }
    }
}

// round 8
// speedup vs baseline: 2.8121x; 1.0263x over previous
#include <cuda_runtime.h>
#include <math.h>

#define BCAPS 32
#define CCAPS 32
#define HH    16
#define WW    36
#define BKK   288
#define CWW   1152
#define NB    16
#define EPSV  1e-10f
#define RSQRT2PI 0.3989422804014327f
#define K1EXP 0.84932180028801904f   /* sqrt(0.5*log2(e)) */

// internal bkk ordering: bkk' = kq*32 + B

// ---------------- scratch ----------------------------------------------------
__device__ float  g_PTm[NB*196*BCAPS*HH];   // pose [b][xy][B][hh]
__device__ float  g_PTe[NB*BCAPS*196*HH];   // pose [b][B][xy][hh]
__device__ float  g_WTm[CCAPS*BKK*HH];      // W    [c][bkk'][hh]
__device__ float  g_AW [NB*WW*BKK];         // act window [b][ww][bkk']
__device__ float  g_RT [NB*CWW*BKK];        // R^T  [b][cww][bkk']
__device__ float  g_AP [NB*BKK*WW*CCAPS];   // a*p  [b][bkk'][ww][c]
__device__ float  g_rowsum[NB*BKK];
__device__ float4 g_EP [NB*WW*HH*CCAPS];    // (A, B, isC, _) [b][ww][h][c]
__device__ float  g_a  [NB*WW*CCAPS];

__device__ __forceinline__ float ex2f(float x) {
    float r; asm("ex2.approx.f32 %0, %1;" : "=f"(r) : "f"(x)); return r;
}

// ---------------- prep kernels -----------------------------------------------
__global__ __launch_bounds__(256) void prep_pose_kernel(const float* __restrict__ poses) {
    int B = blockIdx.x, b = blockIdx.y, t = threadIdx.x;
    __shared__ float tile[16*197];
    for (int idx = t; idx < 16*196; idx += 256) {
        int h = idx / 196, xy = idx % 196;
        tile[h*197 + xy] = poses[(b*512 + h*32 + B)*196 + xy];
    }
    __syncthreads();
    for (int idx = t; idx < 196*16; idx += 256) {
        int xy = idx >> 4, h = idx & 15;
        float v = tile[h*197 + xy];
        g_PTe[((b*32 + B)*196 + xy)*16 + h] = v;
        g_PTm[((b*196 + xy)*32 + B)*16 + h] = v;
    }
}

__global__ __launch_bounds__(256) void prep_W_kernel(const float* __restrict__ W) {
    int o = blockIdx.x*256 + threadIdx.x;
    int c = o / 4608;
    int r = o - c*4608;
    int bkp = r >> 4, h = r & 15;
    int kq = bkp >> 5, B = bkp & 31;
    g_WTm[o] = W[((B*9 + kq)*32 + c)*16 + h];
}

__global__ __launch_bounds__(256) void prep_AW_kernel(const float* __restrict__ act) {
    int idx = blockIdx.x*256 + threadIdx.x;
    if (idx >= NB*WW*BKK) return;
    int b = idx / (WW*BKK);
    int r = idx % (WW*BKK);
    int ww = r / BKK, bkp = r % BKK;
    int kq = bkp >> 5, B = bkp & 31;
    g_AW[idx] = act[((b*32 + B)*14 + (ww/6)*2 + kq/3)*14 + (ww%6)*2 + kq%3];
}

// ---------------- warp multi-value reduction ---------------------------------
// lane l ends with the full-warp sum of value index (l>>1).
__device__ __forceinline__ float reduce16(float v[16], int lane) {
#pragma unroll
    for (int k = 0; k < 8; k++) {
        float send = (lane & 16) ? v[k] : v[k + 8];
        float r = __shfl_xor_sync(0xffffffffu, send, 16);
        v[k] = ((lane & 16) ? v[k + 8] : v[k]) + r;
    }
#pragma unroll
    for (int k = 0; k < 4; k++) {
        float send = (lane & 8) ? v[k] : v[k + 4];
        float r = __shfl_xor_sync(0xffffffffu, send, 8);
        v[k] = ((lane & 8) ? v[k + 4] : v[k]) + r;
    }
#pragma unroll
    for (int k = 0; k < 2; k++) {
        float send = (lane & 4) ? v[k] : v[k + 2];
        float r = __shfl_xor_sync(0xffffffffu, send, 4);
        v[k] = ((lane & 4) ? v[k + 2] : v[k]) + r;
    }
    {
        float send = (lane & 2) ? v[0] : v[1];
        float r = __shfl_xor_sync(0xffffffffu, send, 2);
        v[0] = ((lane & 2) ? v[1] : v[0]) + r;
    }
    return v[0] + __shfl_xor_sync(0xffffffffu, v[0], 1);
}

__device__ __forceinline__ void load16(const float* __restrict__ src, float d[16]) {
    const float4* p4 = reinterpret_cast<const float4*>(src);
    float4 a0 = p4[0], a1 = p4[1], a2 = p4[2], a3 = p4[3];
    d[0]=a0.x; d[1]=a0.y; d[2]=a0.z; d[3]=a0.w;
    d[4]=a1.x; d[5]=a1.y; d[6]=a1.z; d[7]=a1.w;
    d[8]=a2.x; d[9]=a2.y; d[10]=a2.z; d[11]=a2.w;
    d[12]=a3.x; d[13]=a3.y; d[14]=a3.z; d[15]=a3.w;
}

__device__ __forceinline__ void votes4x4(const float Wr[16], const float P[16], float V[16]) {
#pragma unroll
    for (int i = 0; i < 4; i++)
#pragma unroll
        for (int j = 0; j < 4; j++)
            V[i*4+j] = Wr[i*4+0]*P[j]   + Wr[i*4+1]*P[4+j]
                     + Wr[i*4+2]*P[8+j] + Wr[i*4+3]*P[12+j];
}

// ---------------- M step ------------------------------------------------------
// Block = (ww, b, cg): 8 c per block, 96 threads = 3 warps.
// Warp w owns kq triple {3w, 3w+1, 3w+2}; each thread accumulates 3 bkk
// into s1/t2 before the shuffle tree (SHFL cost per bkk cut by 1/3).
__global__ __launch_bounds__(96, 5) void m_step_kernel(
    const float* __restrict__ beta_v, const float* __restrict__ beta_a,
    const float* __restrict__ lambda_, int first_iter, float* __restrict__ out) {
    const int ww = blockIdx.x, b = blockIdx.y, c0 = blockIdx.z * 8;
    const int t = threadIdx.x;
    const int warp = t >> 5, lane = t & 31;
    const int kq0 = warp*3, kq1 = kq0 + 1, kq2 = kq0 + 2;
    const int wx = ww/6, wy = ww%6;
    const int x0 = wx*2 + kq0/3, y0 = wy*2 + kq0%3;
    const int x1 = wx*2 + kq1/3, y1 = wy*2 + kq1%3;
    const int x2 = wx*2 + kq2/3, y2 = wy*2 + kq2%3;

    __shared__ float smP[8*3*34];
    __shared__ float smS0[8*3];
    __shared__ float cost_sm[128];

    float P0[16], P1[16], P2[16];
    load16(&g_PTm[((b*196 + x0*14 + y0)*32 + lane)*16], P0);
    load16(&g_PTm[((b*196 + x1*14 + y1)*32 + lane)*16], P1);
    load16(&g_PTm[((b*196 + x2*14 + y2)*32 + lane)*16], P2);
    const float aw0 = g_AW[(b*WW + ww)*BKK + kq0*32 + lane];
    const float aw1 = g_AW[(b*WW + ww)*BKK + kq1*32 + lane];
    const float aw2 = g_AW[(b*WW + ww)*BKK + kq2*32 + lane];
    const int hslot = (lane >> 1) + ((lane & 1) << 4);
    const size_t rbase = (size_t)b*CWW*BKK;

    for (int cc = 0; cc < 8; cc++) {
        const int c = c0 + cc;
        const size_t rrow = rbase + (size_t)(c*36 + ww)*BKK;
        float rw0, rw1, rw2;
        if (first_iter) {
            const float u = 1.0f/(float)CWW;
            rw0 = u*aw0; rw1 = u*aw1; rw2 = u*aw2;
        } else {
            rw0 = g_RT[rrow + kq0*32 + lane] * aw0;
            rw1 = g_RT[rrow + kq1*32 + lane] * aw1;
            rw2 = g_RT[rrow + kq2*32 + lane] * aw2;
        }

        float Wr[16], V[16], s1[16], t2[16];
        load16(&g_WTm[(c*BKK + kq0*32 + lane)*16], Wr);
        votes4x4(Wr, P0, V);
#pragma unroll
        for (int h = 0; h < 16; h++) {
            float rv = rw0 * V[h];
            s1[h] = rv;
            t2[h] = rv * V[h];
        }
        load16(&g_WTm[(c*BKK + kq1*32 + lane)*16], Wr);
        votes4x4(Wr, P1, V);
#pragma unroll
        for (int h = 0; h < 16; h++) {
            float rv = rw1 * V[h];
            s1[h] += rv;
            t2[h] += rv * V[h];
        }
        load16(&g_WTm[(c*BKK + kq2*32 + lane)*16], Wr);
        votes4x4(Wr, P2, V);
#pragma unroll
        for (int h = 0; h < 16; h++) {
            float rv = rw2 * V[h];
            s1[h] += rv;
            t2[h] += rv * V[h];
        }

        float s0 = rw0 + rw1 + rw2;
#pragma unroll
        for (int o = 16; o > 0; o >>= 1) s0 += __shfl_xor_sync(0xffffffffu, s0, o);

        float S2p = reduce16(t2, lane);
        float S1p = reduce16(s1, lane);

        smP[(cc*3 + warp)*34 + hslot] = (lane & 1) ? S2p : S1p;
        if (lane == 0) smS0[cc*3 + warp] = s0;
    }
    __syncthreads();

    // finalize A: (c = idx>>4, h = idx&15), 128 pairs over 96 threads
    for (int idx = t; idx < 128; idx += 96) {
        int cc = idx >> 4, h = idx & 15;
        const float* base = &smP[cc*3*34];
        float S1 = 0.f, S2 = 0.f, S0 = 0.f;
#pragma unroll
        for (int w2 = 0; w2 < 3; w2++) {
            S1 += base[w2*34 + h];
            S2 += base[w2*34 + 16 + h];
            S0 += smS0[cc*3 + w2];
        }
        float mu = S1 / S0;
        float varr = fmaxf(S2 / S0 - mu*mu, 1e-30f);
        float sg = sqrtf(varr);
        float is = 1.0f / sg;
        cost_sm[idx] = logf(sg + EPSV);
        float A = is * K1EXP;
        float4 e4;
        e4.x = A;
        e4.y = -(mu - EPSV) * A;
        e4.z = is * RSQRT2PI;
        e4.w = 0.f;
        g_EP[((b*WW + ww)*HH + h)*CCAPS + c0 + cc] = e4;
        if (out) out[((b*CCAPS + c0 + cc)*WW + ww)*HH + h] = mu;
    }
    __syncthreads();

    // finalize B: thread t<8 owns c
    if (t < 8) {
        int c = c0 + t;
        float cs = 0.f;
#pragma unroll
        for (int h = 0; h < 16; h++) cs += cost_sm[t*16 + h];
        float S0 = 0.f;
#pragma unroll
        for (int w2 = 0; w2 < 3; w2++) S0 += smS0[t*3 + w2];
        float total = (cs + 16.0f * beta_v[c]) * S0;
        float lam = lambda_[0];
        float a = 1.0f / (1.0f + __expf(-lam * (beta_a[c] - total)));
        g_a[(b*WW + ww)*CCAPS + c] = a;
        if (out) out[NB*CCAPS*WW*HH + (b*CCAPS + c)*WW + ww] = a;
    }
}

// ---------------- E step ------------------------------------------------------
// Block = (Bpair, b): 288 threads, 9 warps = kq; each thread handles BOTH B of
// the pair (e4 float4 read once, used twice). lane = c.
__global__ __launch_bounds__(288, 2) void e_step_kernel(const float* __restrict__ W) {
    int Bp = blockIdx.x, b = blockIdx.y;
    int t = threadIdx.x;
    int warp = t >> 5, lane = t & 31;   // kq, c
    int kq = warp;
    int B0 = Bp*2, B1 = Bp*2 + 1;
    int bkk_out0 = kq*32 + B0;
    int bkk_out1 = kq*32 + B1;
    int kx = kq / 3, ky = kq % 3;

    extern __shared__ float sm[];
    float*  psm  = sm;                               // 2*3136 floats
    float4* esm  = reinterpret_cast<float4*>(sm + 6272);  // 3072 float4
    float*  a_sm = sm + 6272 + 3072*4;               // 192 floats

    for (int idx = t; idx < 3136; idx += 288) {
        psm[idx]        = g_PTe[(size_t)(b*32 + B0)*3136 + idx];
        psm[3136 + idx] = g_PTe[(size_t)(b*32 + B1)*3136 + idx];
    }

    float W0[16], W1[16];
    load16(&W[((B0*9 + kq)*32 + lane)*16], W0);
    load16(&W[((B1*9 + kq)*32 + lane)*16], W1);

    float rs0 = 0.f, rs1 = 0.f;
    for (int tile = 0; tile < 6; tile++) {       // tile == wx
        __syncthreads();
        const float4* src = &g_EP[(size_t)(b*WW + tile*6)*HH*CCAPS];
        for (int idx = t; idx < 3072; idx += 288) esm[idx] = src[idx];
        for (int idx = t; idx < 192; idx += 288)
            a_sm[idx] = g_a[(b*WW + tile*6)*CCAPS + idx];
        __syncthreads();

#pragma unroll
        for (int wl = 0; wl < 6; wl++) {         // wl == wy
            const float* pp = &psm[((2*tile + kx)*14 + 2*wl + ky)*16];
            float P[16], V0[16], V1[16];
#pragma unroll
            for (int q = 0; q < 16; q++) P[q] = pp[q];
            votes4x4(W0, P, V0);
#pragma unroll
            for (int q = 0; q < 16; q++) P[q] = pp[3136 + q];
            votes4x4(W1, P, V1);

            const float4* ep = &esm[(wl*16)*32 + lane];
            float p0 = 0.f, p1 = 0.f;
#pragma unroll
            for (int h = 0; h < 16; h++) {
                float4 e4 = ep[h*32];
                float u0 = fmaf(V0[h], e4.x, e4.y);
                float u1 = fmaf(V1[h], e4.x, e4.y);
                p0 = fmaf(e4.z, ex2f(-u0*u0), p0);
                p1 = fmaf(e4.z, ex2f(-u1*u1), p1);
            }
            float av = a_sm[wl*32 + lane];
            float ap0 = av * p0;
            float ap1 = av * p1;
            g_AP[((size_t)(b*BKK + bkk_out0)*WW + tile*6 + wl)*CCAPS + lane] = ap0;
            g_AP[((size_t)(b*BKK + bkk_out1)*WW + tile*6 + wl)*CCAPS + lane] = ap1;
            rs0 += ap0;
            rs1 += ap1;
        }
    }
#pragma unroll
    for (int o = 16; o > 0; o >>= 1) {
        rs0 += __shfl_xor_sync(0xffffffffu, rs0, o);
        rs1 += __shfl_xor_sync(0xffffffffu, rs1, o);
    }
    if (lane == 0) {
        g_rowsum[b*BKK + bkk_out0] = rs0;
        g_rowsum[b*BKK + bkk_out1] = rs1;
    }
}

// ---------------- normalize + transpose --------------------------------------
__global__ __launch_bounds__(256) void norm_kernel() {
    int ww = blockIdx.x, bt = blockIdx.y, b = blockIdx.z;
    int t = threadIdx.x;
    int tx = t & 31, ty = t >> 5;
    __shared__ float tile[32*33];
    __shared__ float rs[32];
    if (t < 32) rs[t] = g_rowsum[b*BKK + bt*32 + t];
    __syncthreads();
#pragma unroll
    for (int r = 0; r < 4; r++) {
        int bl = ty + r*8;
        float v = g_AP[((size_t)(b*BKK + bt*32 + bl)*WW + ww)*CCAPS + tx];
        tile[bl*33 + tx] = v / rs[bl] + EPSV;
    }
    __syncthreads();
#pragma unroll
    for (int r = 0; r < 4; r++) {
        int cc = ty + r*8;
        g_RT[((size_t)b*CWW + cc*36 + ww)*BKK + bt*32 + tx] = tile[tx*33 + cc];
    }
}

// ---------------- launch ------------------------------------------------------
extern "C" void kernel_launch(void* const* d_in, const int* in_sizes, int n_in,
                              void* d_out, int out_size) {
    const float* poses  = (const float*)d_in[0];
    const float* act    = (const float*)d_in[1];
    const float* W      = (const float*)d_in[2];
    const float* beta_v = (const float*)d_in[3];
    const float* beta_a = (const float*)d_in[4];
    const float* lam    = (const float*)d_in[5];
    float* out = (float*)d_out;

    const int SMEM_E = (6272 + 192)*4 + 3072*16;   // 75008 bytes
    static int attr_done = 0;
    if (!attr_done) {
        cudaFuncSetAttribute(e_step_kernel,
                             cudaFuncAttributeMaxDynamicSharedMemorySize, SMEM_E);
        attr_done = 1;
    }

    prep_pose_kernel<<<dim3(32,16), 256>>>(poses);
    prep_W_kernel<<<576, 256>>>(W);
    prep_AW_kernel<<<(NB*WW*BKK + 255)/256, 256>>>(act);

    for (int it = 0; it < 3; it++) {
        m_step_kernel<<<dim3(36,16,4), 96>>>(beta_v, beta_a, lam,
                                             it == 0 ? 1 : 0,
                                             it == 2 ? out : (float*)nullptr);
        if (it < 2) {
            e_step_kernel<<<dim3(16,16), 288, SMEM_E>>>(W);
            norm_kernel<<<dim3(36,9,16), 256>>>();
        }
    }
}